// round 1
// baseline (speedup 1.0000x reference)
#include <cuda_runtime.h>
#include <cuda_bf16.h>
#include <cstdint>

// ---- problem constants ----
#define T1n 128
#define T2n 512
#define TPn 8
#define Hn  16
#define Kn  4
#define Cn  129   // 2*K*H+1
#define Dn  256

// ---- device scratch (no allocations allowed) ----
__device__ float  g_inv1[T1n];
__device__ float  g_inv2[T2n];
__device__ float  g_e2T[Dn * T2n];            // normalized, transposed emb_T2
__device__ float  g_val[T1n * T2n];           // val_v
__device__ float4 g_pack[T1n * TPn * T2n];    // {aw, w2, ap bits, 0} per (i,t,j)
__device__ float  g_SA[T1n * TPn];            // sum_j m*A^2 per (i,t)

// ---------------------------------------------------------------------------
// K1: row inverse norms for both embedding matrices (640 rows)
// ---------------------------------------------------------------------------
__global__ void k_norms(const float* __restrict__ e1, const float* __restrict__ e2) {
    int row = blockIdx.x;
    const float* src = (row < T1n) ? (e1 + row * Dn) : (e2 + (row - T1n) * Dn);
    int tid = threadIdx.x;   // 128
    float s = 0.f;
    #pragma unroll
    for (int k = tid; k < Dn; k += 128) { float x = src[k]; s += x * x; }
    for (int o = 16; o; o >>= 1) s += __shfl_down_sync(0xffffffffu, s, o);
    __shared__ float sm[4];
    if ((tid & 31) == 0) sm[tid >> 5] = s;
    __syncthreads();
    if (tid == 0) {
        float inv = rsqrtf(sm[0] + sm[1] + sm[2] + sm[3]);
        if (row < T1n) g_inv1[row] = inv; else g_inv2[row - T1n] = inv;
    }
}

// ---------------------------------------------------------------------------
// K2: transpose + normalize emb_T2 -> g_e2T[k][j]
// ---------------------------------------------------------------------------
__global__ void k_transpose(const float* __restrict__ e2) {
    int j = blockIdx.x;          // 512
    int k = threadIdx.x;         // 256
    float inv = g_inv2[j];
    g_e2T[k * T2n + j] = e2[j * Dn + k] * inv;
}

// ---------------------------------------------------------------------------
// K3: val_v[i][j] = <e1_i/|e1_i|, e2_j/|e2_j|>. Block per i, thread per j.
// ---------------------------------------------------------------------------
__global__ __launch_bounds__(512) void k_gemm(const float* __restrict__ e1) {
    int i = blockIdx.x;
    int j = threadIdx.x;         // 512
    __shared__ float s1[Dn];
    if (j < Dn) s1[j] = e1[i * Dn + j] * g_inv1[i];
    __syncthreads();
    float acc = 0.f;
    #pragma unroll 8
    for (int k = 0; k < Dn; k++) acc = fmaf(s1[k], g_e2T[k * T2n + j], acc);
    g_val[i * T2n + j] = acc;
}

// ---------------------------------------------------------------------------
// K4: build per-(i,t,j) packed {aw, w2, |pos| bits} and per-(i,t) SA.
//   A = (dsum - dis_t)/8 - val ; aw = m*A*sign(pos)/128 ; w2 = m/16384
// ---------------------------------------------------------------------------
__global__ __launch_bounds__(512) void k_build(const int* __restrict__ sta,
                                               const int* __restrict__ pos,
                                               const unsigned* __restrict__ mask) {
    int i = blockIdx.x;
    int j = threadIdx.x;         // 512
    int st[TPn], pv[TPn];
    #pragma unroll
    for (int t = 0; t < TPn; t++) st[t] = sta[i * TPn + t];
    #pragma unroll
    for (int t = 0; t < TPn; t++) pv[t] = pos[j * TPn + t];
    // mask is bool in the reference; as float32 (0.0/1.0) or int32 (0/1) the
    // 32-bit word is nonzero iff true.
    float fm  = (mask[i * T2n + j] != 0u) ? 1.0f : 0.0f;
    float val = g_val[i * T2n + j];

    float dis[TPn], spf[TPn];
    int   ab[TPn];
    float dsum = 0.f;
    #pragma unroll
    for (int t = 0; t < TPn; t++) {
        int a = st[t] < 0 ? -st[t] : st[t];
        int b = pv[t] < 0 ? -pv[t] : pv[t];
        ab[t] = b;
        float sg = ((st[t] ^ pv[t]) < 0) ? -1.0f : 1.0f;   // sign product
        int v = (a ^ b) + 1;
        int p; asm("bfind.u32 %0, %1;" : "=r"(p) : "r"(v));
        dis[t] = sg * (float)(15 - p) * (1.0f / 16.0f);
        spf[t] = (pv[t] < 0) ? -1.0f : 1.0f;
        dsum += dis[t];
    }
    float sacc[TPn];
    #pragma unroll
    for (int t = 0; t < TPn; t++) {
        float A  = (dsum - dis[t]) * 0.125f - val;
        float aw = fm * A * spf[t] * (1.0f / 128.0f);
        float w2 = fm * (1.0f / 16384.0f);
        g_pack[(i * TPn + t) * T2n + j] =
            make_float4(aw, w2, __int_as_float(ab[t]), 0.0f);
        sacc[t] = fm * A * A;
    }
    // block-reduce SA per t
    __shared__ float red[16][TPn];
    #pragma unroll
    for (int t = 0; t < TPn; t++)
        for (int o = 16; o; o >>= 1)
            sacc[t] += __shfl_down_sync(0xffffffffu, sacc[t], o);
    int w = j >> 5, l = j & 31;
    if (l == 0) {
        #pragma unroll
        for (int t = 0; t < TPn; t++) red[w][t] = sacc[t];
    }
    __syncthreads();
    if (j < TPn) {
        float s = 0.f;
        #pragma unroll
        for (int ww = 0; ww < 16; ww++) s += red[ww][j];
        g_SA[i * TPn + j] = s;
    }
}

// ---------------------------------------------------------------------------
// K5: main loss kernel. Grid (i, t); 288 threads.
//   thread: candidate c = tid>>2 (0..64; 64 == sta), j-chunk = tid&3.
//   Mirror candidates (65..128) derived algebraically: loss± = SA+Sq ± 2*sc*S2.
// ---------------------------------------------------------------------------
__global__ __launch_bounds__(288) void k_main(const int* __restrict__ sta,
                                              const int* __restrict__ rmask,
                                              float* __restrict__ out) {
    int i = blockIdx.x, t = blockIdx.y;
    __shared__ float4 s_pack[T2n];        // 8 KB
    __shared__ float2 s_tab[18 * 32];     // lane-replicated {f, f^2}, p in [0,17]
    int tid = threadIdx.x;

    for (int idx = tid; idx < T2n; idx += 288)
        s_pack[idx] = g_pack[(i * TPn + t) * T2n + idx];
    for (int idx = tid; idx < 18 * 32; idx += 288) {
        float f = (float)(15 - (idx >> 5));
        s_tab[idx] = make_float2(f, f * f);
    }
    __syncthreads();

    int c = tid >> 2; if (c > 64) c = 64;   // tids >=260 run harmlessly
    int chunk = tid & 3;
    int stav = sta[i * TPn + t];
    int cand;
    if (c < 64) {
        int h = c >> 2, k = c & 3;
        int rm = rmask[((i * Hn + h) * Kn + k) * TPn + t];
        cand = (stav ^ (1 << h)) ^ (rm & ((1 << h) - 1));
    } else {
        cand = stav;
    }
    int   ac = cand < 0 ? -cand : cand;
    float sc = cand < 0 ? -1.0f : 1.0f;
    const float2* tabl = s_tab + (tid & 31);
    const float4* pp   = s_pack + chunk;

    float S2 = 0.f, Sq = 0.f;
    #pragma unroll 8
    for (int jj = 0; jj < 128; jj++) {
        float4 pk = pp[jj << 2];
        int v = (ac ^ __float_as_int(pk.z)) + 1;
        int p; asm("bfind.u32 %0, %1;" : "=r"(p) : "r"(v));
        float2 ff = tabl[p << 5];
        S2 = fmaf(pk.x, ff.x, S2);
        Sq = fmaf(pk.y, ff.y, Sq);
    }
    // reduce the 4 j-chunks (lanes 4m..4m+3 share a candidate)
    S2 += __shfl_down_sync(0xffffffffu, S2, 2);
    S2 += __shfl_down_sync(0xffffffffu, S2, 1);
    Sq += __shfl_down_sync(0xffffffffu, Sq, 2);
    Sq += __shfl_down_sync(0xffffffffu, Sq, 1);

    if ((tid & 3) == 0 && tid < 260) {
        float base = g_SA[i * TPn + t] + Sq;
        float twos = 2.0f * sc * S2;
        float lp   = base + twos;
        if (c == 64) {
            out[(i * Cn + 64) * TPn + t] = lp;
        } else {
            out[(i * Cn + c) * TPn + t] = lp;
            out[(i * Cn + 65 + c) * TPn + t] = (cand == 0) ? lp : (base - twos);
        }
    }
}

// ---------------------------------------------------------------------------
extern "C" void kernel_launch(void* const* d_in, const int* in_sizes, int n_in,
                              void* d_out, int out_size) {
    const float*    emb1 = (const float*)d_in[0];
    const float*    emb2 = (const float*)d_in[1];
    const int*      sta  = (const int*)d_in[2];
    const int*      pos  = (const int*)d_in[3];
    const unsigned* mask = (const unsigned*)d_in[4];
    const int*      rm   = (const int*)d_in[5];
    float*          out  = (float*)d_out;

    k_norms<<<T1n + T2n, 128>>>(emb1, emb2);
    k_transpose<<<T2n, Dn>>>(emb2);
    k_gemm<<<T1n, T2n>>>(emb1);
    k_build<<<T1n, T2n>>>(sta, pos, mask);
    k_main<<<dim3(T1n, TPn), 288>>>(sta, rm, out);
}

// round 2
// speedup vs baseline: 1.1356x; 1.1356x over previous
#include <cuda_runtime.h>
#include <cuda_bf16.h>
#include <cstdint>

// ---- problem constants ----
#define T1n 128
#define T2n 512
#define TPn 8
#define Hn  16
#define Kn  4
#define Cn  129   // 2*K*H+1
#define Dn  256

// ---- device scratch ----
__device__ float  g_e2T[Dn * T2n];            // normalized, transposed emb_T2
__device__ float  g_val[T1n * T2n];           // val_v
__device__ float2 g_pack[T1n * TPn * T2n];    // compacted {aw, |pos| bits} per (i,t,j')
__device__ float  g_SA[T1n * TPn];            // sum_j m*A^2 per (i,t)
__device__ int    g_cnt[T1n];                 // compacted count per i

// ---------------------------------------------------------------------------
// K1: normalize + transpose emb_T2 -> g_e2T[k][j]  (fused row norm)
// ---------------------------------------------------------------------------
__global__ __launch_bounds__(256) void k_t2(const float* __restrict__ e2) {
    int j = blockIdx.x;          // 512
    int k = threadIdx.x;         // 256
    float x = e2[j * Dn + k];
    float ss = x * x;
    for (int o = 16; o; o >>= 1) ss += __shfl_down_sync(0xffffffffu, ss, o);
    __shared__ float sm[8];
    __shared__ float sinv;
    if ((k & 31) == 0) sm[k >> 5] = ss;
    __syncthreads();
    if (k == 0) {
        float s = 0.f;
        #pragma unroll
        for (int w = 0; w < 8; w++) s += sm[w];
        sinv = rsqrtf(s);
    }
    __syncthreads();
    g_e2T[k * T2n + j] = x * sinv;
}

// ---------------------------------------------------------------------------
// K2: val_v. Block = 4 rows of i (32 blocks x 512 thr). e1 norms computed here.
// ---------------------------------------------------------------------------
__global__ __launch_bounds__(512) void k_gemm(const float* __restrict__ e1) {
    int i0 = blockIdx.x * 4;
    int tid = threadIdx.x;
    int q = tid >> 7, r = tid & 127;     // q: which of 4 rows, r: 0..127
    __shared__ float s1[4][Dn];
    __shared__ float red[4][4];
    __shared__ float sinv[4];

    float a0 = e1[(i0 + q) * Dn + r];
    float a1 = e1[(i0 + q) * Dn + 128 + r];
    float ss = a0 * a0 + a1 * a1;
    for (int o = 16; o; o >>= 1) ss += __shfl_down_sync(0xffffffffu, ss, o);
    if ((r & 31) == 0) red[q][r >> 5] = ss;
    __syncthreads();
    if (tid < 4) sinv[tid] = rsqrtf(red[tid][0] + red[tid][1] + red[tid][2] + red[tid][3]);
    __syncthreads();
    float inv = sinv[q];
    s1[q][r] = a0 * inv;
    s1[q][r + 128] = a1 * inv;
    __syncthreads();

    int j = tid;                          // 512 columns
    float acc0 = 0.f, acc1 = 0.f, acc2 = 0.f, acc3 = 0.f;
    #pragma unroll 4
    for (int k = 0; k < Dn; k++) {
        float b = g_e2T[k * T2n + j];
        acc0 = fmaf(s1[0][k], b, acc0);
        acc1 = fmaf(s1[1][k], b, acc1);
        acc2 = fmaf(s1[2][k], b, acc2);
        acc3 = fmaf(s1[3][k], b, acc3);
    }
    g_val[(i0 + 0) * T2n + j] = acc0;
    g_val[(i0 + 1) * T2n + j] = acc1;
    g_val[(i0 + 2) * T2n + j] = acc2;
    g_val[(i0 + 3) * T2n + j] = acc3;
}

// ---------------------------------------------------------------------------
// K3: build per-(i,t) compacted {aw, |pos|} lists + SA + cnt.
//   A = (dsum - dis_t)/8 - val ; aw = A*sign(pos)/128 (masked-in only)
// ---------------------------------------------------------------------------
__global__ __launch_bounds__(512) void k_build(const int* __restrict__ sta,
                                               const int* __restrict__ pos,
                                               const unsigned* __restrict__ mask) {
    int i = blockIdx.x;
    int j = threadIdx.x;         // 512
    int st[TPn];
    #pragma unroll
    for (int t = 0; t < TPn; t++) st[t] = sta[i * TPn + t];
    int4 p0 = ((const int4*)pos)[j * 2];
    int4 p1 = ((const int4*)pos)[j * 2 + 1];
    int pv[TPn] = {p0.x, p0.y, p0.z, p0.w, p1.x, p1.y, p1.z, p1.w};

    bool m = (mask[i * T2n + j] != 0u);
    float val = g_val[i * T2n + j];

    float dis[TPn], spf[TPn];
    int   ab[TPn];
    float dsum = 0.f;
    #pragma unroll
    for (int t = 0; t < TPn; t++) {
        int a = st[t] < 0 ? -st[t] : st[t];
        int b = pv[t] < 0 ? -pv[t] : pv[t];
        ab[t] = b;
        float sg = ((st[t] ^ pv[t]) < 0) ? -1.0f : 1.0f;
        int v = (a ^ b) + 1;
        int p; asm("bfind.u32 %0, %1;" : "=r"(p) : "r"(v));
        dis[t] = sg * (float)(15 - p) * (1.0f / 16.0f);
        spf[t] = (pv[t] < 0) ? -1.0f : 1.0f;
        dsum += dis[t];
    }

    // compaction position via ballot prefix (deterministic)
    unsigned ball = __ballot_sync(0xffffffffu, m);
    int wid = j >> 5, lane = j & 31;
    __shared__ int wcnt[16], wbase[16];
    if (lane == 0) wcnt[wid] = __popc(ball);
    __syncthreads();
    if (j == 0) {
        int s = 0;
        #pragma unroll
        for (int w = 0; w < 16; w++) { wbase[w] = s; s += wcnt[w]; }
        g_cnt[i] = s;
    }
    __syncthreads();
    int posj = wbase[wid] + __popc(ball & ((1u << lane) - 1u));

    float sacc[TPn];
    #pragma unroll
    for (int t = 0; t < TPn; t++) {
        float A = (dsum - dis[t]) * 0.125f - val;
        if (m) {
            g_pack[(i * TPn + t) * T2n + posj] =
                make_float2(A * spf[t] * (1.0f / 128.0f), __int_as_float(ab[t]));
        }
        sacc[t] = m ? A * A : 0.0f;
    }

    // block-reduce SA per t
    __shared__ float red[16][TPn];
    #pragma unroll
    for (int t = 0; t < TPn; t++)
        for (int o = 16; o; o >>= 1)
            sacc[t] += __shfl_down_sync(0xffffffffu, sacc[t], o);
    if (lane == 0) {
        #pragma unroll
        for (int t = 0; t < TPn; t++) red[wid][t] = sacc[t];
    }
    __syncthreads();
    if (j < TPn) {
        float s = 0.f;
        #pragma unroll
        for (int ww = 0; ww < 16; ww++) s += red[ww][j];
        g_SA[i * TPn + j] = s;
    }
}

// ---------------------------------------------------------------------------
// K4: main loss kernel. Grid (i,t); 288 threads.
//   tid: pair = tid>>3 in [0,32], chunk = tid&7.
//   Thread handles candidates c0=pair and c1=pair+33 over j-chunk (stride 8).
//   Mirrors (65..128) derived algebraically: loss± = SA + Sq/16384 ± 2*sc*S2.
// ---------------------------------------------------------------------------
__device__ __forceinline__ int make_cand(int c, int stav, const int* rm, int i, int t) {
    if (c < 64) {
        int h = c >> 2, k = c & 3;
        int r = rm[((i * Hn + h) * Kn + k) * TPn + t];
        return (stav ^ (1 << h)) ^ (r & ((1 << h) - 1));
    }
    return stav;
}

__global__ __launch_bounds__(288) void k_main(const int* __restrict__ sta,
                                              const int* __restrict__ rmask,
                                              float* __restrict__ out) {
    int i = blockIdx.x, t = blockIdx.y;
    __shared__ float2 s_pk[T2n];          // 4 KB
    __shared__ float  s_f[18 * 32];       // lane-replicated f(p) = 15-p
    int tid = threadIdx.x;
    int cnt = g_cnt[i];

    const float2* gp = g_pack + (i * TPn + t) * T2n;
    for (int idx = tid; idx < cnt; idx += 288) s_pk[idx] = gp[idx];
    for (int idx = tid; idx < 18 * 32; idx += 288) s_f[idx] = (float)(15 - (idx >> 5));
    __syncthreads();

    int pr = tid >> 3; if (pr > 32) pr = 32;   // tids 264..287: clamped, no store
    int chunk = tid & 7;
    int stav = sta[i * TPn + t];
    int c0 = pr, c1 = pr + 33;                 // c1==65 is a dummy
    int cand0 = make_cand(c0, stav, rmask, i, t);
    int cand1 = (c1 <= 64) ? make_cand(c1, stav, rmask, i, t) : stav;
    int ac0 = cand0 < 0 ? -cand0 : cand0;
    int ac1 = cand1 < 0 ? -cand1 : cand1;
    const float* tab = s_f + (tid & 31);

    float S20 = 0.f, Sq0 = 0.f, S21 = 0.f, Sq1 = 0.f;
    #pragma unroll 4
    for (int jj = chunk; jj < cnt; jj += 8) {
        float2 pk = s_pk[jj];
        int ap = __float_as_int(pk.y);
        int v0 = (ac0 ^ ap) + 1;
        int v1 = (ac1 ^ ap) + 1;
        int q0, q1;
        asm("bfind.u32 %0, %1;" : "=r"(q0) : "r"(v0));
        asm("bfind.u32 %0, %1;" : "=r"(q1) : "r"(v1));
        float f0 = tab[q0 << 5];
        float f1 = tab[q1 << 5];
        S20 = fmaf(pk.x, f0, S20);
        Sq0 = fmaf(f0, f0, Sq0);
        S21 = fmaf(pk.x, f1, S21);
        Sq1 = fmaf(f1, f1, Sq1);
    }
    // reduce over the 8 j-chunks (contiguous lane groups of 8)
    #pragma unroll
    for (int o = 4; o; o >>= 1) {
        S20 += __shfl_down_sync(0xffffffffu, S20, o);
        Sq0 += __shfl_down_sync(0xffffffffu, Sq0, o);
        S21 += __shfl_down_sync(0xffffffffu, S21, o);
        Sq1 += __shfl_down_sync(0xffffffffu, Sq1, o);
    }

    if (chunk == 0 && tid < 264) {
        float SA = g_SA[i * TPn + t];
        // c0 in [0,32]: always a res candidate -> direct + mirror
        {
            float base = SA + Sq0 * (1.0f / 16384.0f);
            float sc   = cand0 < 0 ? -1.0f : 1.0f;
            float tw   = 2.0f * sc * S20;
            float lp   = base + tw;
            out[(i * Cn + c0) * TPn + t] = lp;
            out[(i * Cn + 65 + c0) * TPn + t] = (cand0 == 0) ? lp : (base - tw);
        }
        if (c1 <= 64) {
            float base = SA + Sq1 * (1.0f / 16384.0f);
            float sc   = cand1 < 0 ? -1.0f : 1.0f;
            float tw   = 2.0f * sc * S21;
            float lp   = base + tw;
            out[(i * Cn + c1) * TPn + t] = lp;
            if (c1 < 64)
                out[(i * Cn + 65 + c1) * TPn + t] = (cand1 == 0) ? lp : (base - tw);
        }
    }
}

// ---------------------------------------------------------------------------
extern "C" void kernel_launch(void* const* d_in, const int* in_sizes, int n_in,
                              void* d_out, int out_size) {
    const float*    emb1 = (const float*)d_in[0];
    const float*    emb2 = (const float*)d_in[1];
    const int*      sta  = (const int*)d_in[2];
    const int*      pos  = (const int*)d_in[3];
    const unsigned* mask = (const unsigned*)d_in[4];
    const int*      rm   = (const int*)d_in[5];
    float*          out  = (float*)d_out;

    k_t2<<<T2n, Dn>>>(emb2);
    k_gemm<<<T1n / 4, 512>>>(emb1);
    k_build<<<T1n, T2n>>>(sta, pos, mask);
    k_main<<<dim3(T1n, TPn), 288>>>(sta, rm, out);
}

// round 3
// speedup vs baseline: 1.2479x; 1.0988x over previous
#include <cuda_runtime.h>
#include <cuda_bf16.h>
#include <cstdint>

// ---- problem constants ----
#define T1n 128
#define T2n 512
#define TPn 8
#define Hn  16
#define Kn  4
#define Cn  129   // 2*K*H+1
#define Dn  256

// ---- device scratch ----
__device__ float g_val[T1n * T2n];   // val_v

// ---------------------------------------------------------------------------
// K1: val_v[i][j] = <e1_i/|e1_i|, e2_j/|e2_j|>.
//   Grid (32,4): block = 4 i-rows x 128 j-cols. 512 threads: (il=tid>>7, jl=tid&127).
//   Reads raw e2 rows (L1-friendly: 8 successive float4 hits per 128B line),
//   computes row ssq inline (4x redundant across il, trivial).
// ---------------------------------------------------------------------------
__global__ __launch_bounds__(512) void k_val(const float* __restrict__ e1,
                                             const float* __restrict__ e2) {
    int i0 = blockIdx.x * 4;
    int j0 = blockIdx.y * 128;
    int tid = threadIdx.x;
    int q = tid >> 7, r = tid & 127;

    __shared__ float s1[4][Dn];
    __shared__ float red[4][4];
    __shared__ float sinv[4];

    // e1 row norms (4 rows, computed in-block)
    float a0 = e1[(i0 + q) * Dn + r];
    float a1 = e1[(i0 + q) * Dn + 128 + r];
    float ss = a0 * a0 + a1 * a1;
    for (int o = 16; o; o >>= 1) ss += __shfl_down_sync(0xffffffffu, ss, o);
    if ((r & 31) == 0) red[q][r >> 5] = ss;
    __syncthreads();
    if (tid < 4) sinv[tid] = rsqrtf(red[tid][0] + red[tid][1] + red[tid][2] + red[tid][3]);
    __syncthreads();
    float inv = sinv[q];
    s1[q][r] = a0 * inv;
    s1[q][r + 128] = a1 * inv;
    __syncthreads();

    int j = j0 + r;
    const float4* row  = (const float4*)(e2 + j * Dn);
    const float4* arow = (const float4*)(&s1[q][0]);
    float dot = 0.f, ssq = 0.f;
    #pragma unroll 8
    for (int kk = 0; kk < Dn / 4; kk++) {
        float4 b = row[kk];
        float4 a = arow[kk];
        dot = fmaf(a.x, b.x, dot); ssq = fmaf(b.x, b.x, ssq);
        dot = fmaf(a.y, b.y, dot); ssq = fmaf(b.y, b.y, ssq);
        dot = fmaf(a.z, b.z, dot); ssq = fmaf(b.z, b.z, ssq);
        dot = fmaf(a.w, b.w, dot); ssq = fmaf(b.w, b.w, ssq);
    }
    g_val[(i0 + q) * T2n + j] = dot * rsqrtf(ssq);
}

// ---------------------------------------------------------------------------
// K2: fused build + loss. Grid (i,t) = (128,8); 288 threads (9 warps).
//   Phase 1: each thread handles j = tid, tid+288; computes distances over all
//     8 t' (for dsum), A/aw for own t, deterministic ballot+scan compaction
//     into smem pack {packed(aw,1.0), |pos|}, SA block-reduce.
//   Phase 2: tid = pair(0..32)*8 + chunk; candidates c0=pair, c1=pair+33;
//     inner loop: LDS.128 pack, per cand XOR/+1/FLO/IMAD/LDS.64/FFMA2 (f32x2
//     packs S2 += aw*f and Sq += f^2 into one instruction).
//   Mirrors (65..128) algebraic: loss± = SA + Sq/16384 ± 2*sc*S2.
// ---------------------------------------------------------------------------
__device__ __forceinline__ int make_cand(int c, int stav, const int* rm, int i, int t) {
    if (c < 64) {
        int h = c >> 2, k = c & 3;
        int r = rm[((i * Hn + h) * Kn + k) * TPn + t];
        return (stav ^ (1 << h)) ^ (r & ((1 << h) - 1));
    }
    return stav;
}

__global__ __launch_bounds__(288) void k_mega(const int* __restrict__ sta,
                                              const int* __restrict__ pos,
                                              const unsigned* __restrict__ mask,
                                              const int* __restrict__ rmask,
                                              float* __restrict__ out) {
    int i = blockIdx.x, t = blockIdx.y;
    int tid = threadIdx.x;
    int lane = tid & 31, w = tid >> 5;          // 9 warps

    __shared__ ulonglong2 s_pk[T2n];            // 8 KB: {bits{aw,1.0f}, |pos|}
    __shared__ float2     s_tab[18 * 32];       // lane-replicated {f, f^2}
    __shared__ int        s_st[TPn];
    __shared__ int        s_wcnt[18];
    __shared__ int        s_base[18];
    __shared__ int        s_cnt;
    __shared__ float      s_sared[9];
    __shared__ float      s_SA;

    for (int idx = tid; idx < 18 * 32; idx += 288) {
        float f = (float)(15 - (idx >> 5));
        s_tab[idx] = make_float2(f, f * f);
    }
    if (tid < TPn) s_st[tid] = sta[i * TPn + tid];
    __syncthreads();

    int st[TPn];
    #pragma unroll
    for (int tt = 0; tt < TPn; tt++) st[tt] = s_st[tt];

    // ---- phase 1: build compacted pack ----
    unsigned ballR[2];
    float    awR[2];
    int      abR[2];
    bool     mR[2];
    float    sacc = 0.f;
    #pragma unroll
    for (int rr = 0; rr < 2; rr++) {
        int j = rr * 288 + tid;
        bool valid = (j < T2n);
        int jc = valid ? j : 0;
        int4 p0 = ((const int4*)pos)[jc * 2];
        int4 p1 = ((const int4*)pos)[jc * 2 + 1];
        int pv[TPn] = {p0.x, p0.y, p0.z, p0.w, p1.x, p1.y, p1.z, p1.w};
        bool m = valid && (mask[i * T2n + jc] != 0u);
        float val = g_val[i * T2n + jc];

        float dsum = 0.f, dis_t = 0.f, spf_t = 1.f;
        int   ab_t = 0;
        #pragma unroll
        for (int tt = 0; tt < TPn; tt++) {
            int a = st[tt] < 0 ? -st[tt] : st[tt];
            int b = pv[tt] < 0 ? -pv[tt] : pv[tt];
            float sg = ((st[tt] ^ pv[tt]) < 0) ? -1.0f : 1.0f;
            int v = (a ^ b) + 1;
            int p; asm("bfind.u32 %0, %1;" : "=r"(p) : "r"(v));
            float d = sg * (float)(15 - p) * (1.0f / 16.0f);
            dsum += d;
            if (tt == t) { dis_t = d; ab_t = b; spf_t = (pv[tt] < 0) ? -1.0f : 1.0f; }
        }
        float A = (dsum - dis_t) * 0.125f - val;
        awR[rr] = A * spf_t * (1.0f / 128.0f);
        abR[rr] = ab_t;
        mR[rr]  = m;
        ballR[rr] = __ballot_sync(0xffffffffu, m);
        if (m) sacc = fmaf(A, A, sacc);
    }
    if (lane == 0) { s_wcnt[w] = __popc(ballR[0]); s_wcnt[9 + w] = __popc(ballR[1]); }
    for (int o = 16; o; o >>= 1) sacc += __shfl_down_sync(0xffffffffu, sacc, o);
    if (lane == 0) s_sared[w] = sacc;
    __syncthreads();
    if (tid == 0) {
        int s = 0;
        #pragma unroll
        for (int x = 0; x < 18; x++) { s_base[x] = s; s += s_wcnt[x]; }
        s_cnt = s;
        float sa = 0.f;
        #pragma unroll
        for (int x = 0; x < 9; x++) sa += s_sared[x];
        s_SA = sa;
    }
    __syncthreads();
    unsigned lt = (1u << lane) - 1u;
    #pragma unroll
    for (int rr = 0; rr < 2; rr++) {
        if (mR[rr]) {
            int slot = s_base[rr * 9 + w] + __popc(ballR[rr] & lt);
            unsigned long long lo = ((unsigned long long)0x3F800000u << 32) |
                                    (unsigned long long)__float_as_uint(awR[rr]);
            s_pk[slot] = make_ulonglong2(lo, (unsigned long long)(unsigned)abR[rr]);
        }
    }
    __syncthreads();
    int cnt = s_cnt;

    // ---- phase 2: main loop ----
    int pr = tid >> 3; if (pr > 32) pr = 32;    // tids 264..287 clamped, no store
    int chunk = tid & 7;
    int stav = st[t];
    int c0 = pr, c1 = pr + 33;                  // c1==65 is a dummy
    int cand0 = make_cand(c0, stav, rmask, i, t);
    int cand1 = (c1 <= 64) ? make_cand(c1, stav, rmask, i, t) : stav;
    int ac0 = cand0 < 0 ? -cand0 : cand0;
    int ac1 = cand1 < 0 ? -cand1 : cand1;
    const unsigned long long* tabl =
        reinterpret_cast<const unsigned long long*>(s_tab) + lane;

    unsigned long long acc0 = 0ull, acc1 = 0ull;   // {S2, Sq} packed
    #pragma unroll 4
    for (int jj = chunk; jj < cnt; jj += 8) {
        ulonglong2 pk = s_pk[jj];
        int ap = (int)(unsigned)pk.y;
        int v0 = (ac0 ^ ap) + 1;
        int v1 = (ac1 ^ ap) + 1;
        int q0, q1;
        asm("bfind.u32 %0, %1;" : "=r"(q0) : "r"(v0));
        asm("bfind.u32 %0, %1;" : "=r"(q1) : "r"(v1));
        unsigned long long f0 = tabl[q0 << 5];
        unsigned long long f1 = tabl[q1 << 5];
        asm("fma.rn.f32x2 %0, %1, %2, %0;" : "+l"(acc0) : "l"(pk.x), "l"(f0));
        asm("fma.rn.f32x2 %0, %1, %2, %0;" : "+l"(acc1) : "l"(pk.x), "l"(f1));
    }
    float S20, Sq0, S21, Sq1;
    asm("mov.b64 {%0, %1}, %2;" : "=f"(S20), "=f"(Sq0) : "l"(acc0));
    asm("mov.b64 {%0, %1}, %2;" : "=f"(S21), "=f"(Sq1) : "l"(acc1));
    #pragma unroll
    for (int o = 4; o; o >>= 1) {
        S20 += __shfl_down_sync(0xffffffffu, S20, o);
        Sq0 += __shfl_down_sync(0xffffffffu, Sq0, o);
        S21 += __shfl_down_sync(0xffffffffu, S21, o);
        Sq1 += __shfl_down_sync(0xffffffffu, Sq1, o);
    }

    if (chunk == 0 && tid < 264) {
        float SA = s_SA;
        {
            float base = SA + Sq0 * (1.0f / 16384.0f);
            float sc   = cand0 < 0 ? -1.0f : 1.0f;
            float tw   = 2.0f * sc * S20;
            float lp   = base + tw;
            out[(i * Cn + c0) * TPn + t] = lp;
            out[(i * Cn + 65 + c0) * TPn + t] = (cand0 == 0) ? lp : (base - tw);
        }
        if (c1 <= 64) {
            float base = SA + Sq1 * (1.0f / 16384.0f);
            float sc   = cand1 < 0 ? -1.0f : 1.0f;
            float tw   = 2.0f * sc * S21;
            float lp   = base + tw;
            out[(i * Cn + c1) * TPn + t] = lp;
            if (c1 < 64)
                out[(i * Cn + 65 + c1) * TPn + t] = (cand1 == 0) ? lp : (base - tw);
        }
    }
}

// ---------------------------------------------------------------------------
extern "C" void kernel_launch(void* const* d_in, const int* in_sizes, int n_in,
                              void* d_out, int out_size) {
    const float*    emb1 = (const float*)d_in[0];
    const float*    emb2 = (const float*)d_in[1];
    const int*      sta  = (const int*)d_in[2];
    const int*      pos  = (const int*)d_in[3];
    const unsigned* mask = (const unsigned*)d_in[4];
    const int*      rm   = (const int*)d_in[5];
    float*          out  = (float*)d_out;

    k_val<<<dim3(32, 4), 512>>>(emb1, emb2);
    k_mega<<<dim3(T1n, TPn), 288>>>(sta, pos, mask, rm, out);
}

// round 4
// speedup vs baseline: 1.3741x; 1.1012x over previous
#include <cuda_runtime.h>
#include <cuda_bf16.h>
#include <cstdint>

// ---- problem constants ----
#define T1n 128
#define T2n 512
#define TPn 8
#define Hn  16
#define Kn  4
#define Cn  129   // 2*K*H+1
#define Dn  256

// ---- device scratch ----
__device__ float g_val[T1n * T2n];   // val_v

// ---------------------------------------------------------------------------
// K1: val_v[i][j] = <e1_i/|e1_i|, e2_j/|e2_j|>.
//   Grid (32,4): block = 4 i-rows x 128 j-cols, 512 threads.
// ---------------------------------------------------------------------------
__global__ __launch_bounds__(512) void k_val(const float* __restrict__ e1,
                                             const float* __restrict__ e2) {
    int i0 = blockIdx.x * 4;
    int j0 = blockIdx.y * 128;
    int tid = threadIdx.x;
    int q = tid >> 7, r = tid & 127;

    __shared__ float s1[4][Dn];
    __shared__ float red[4][4];
    __shared__ float sinv[4];

    float a0 = e1[(i0 + q) * Dn + r];
    float a1 = e1[(i0 + q) * Dn + 128 + r];
    float ss = a0 * a0 + a1 * a1;
    for (int o = 16; o; o >>= 1) ss += __shfl_down_sync(0xffffffffu, ss, o);
    if ((r & 31) == 0) red[q][r >> 5] = ss;
    __syncthreads();
    if (tid < 4) sinv[tid] = rsqrtf(red[tid][0] + red[tid][1] + red[tid][2] + red[tid][3]);
    __syncthreads();
    float inv = sinv[q];
    s1[q][r] = a0 * inv;
    s1[q][r + 128] = a1 * inv;
    __syncthreads();

    int j = j0 + r;
    const float4* row  = (const float4*)(e2 + j * Dn);
    const float4* arow = (const float4*)(&s1[q][0]);
    float dot = 0.f, ssq = 0.f;
    #pragma unroll 8
    for (int kk = 0; kk < Dn / 4; kk++) {
        float4 b = row[kk];
        float4 a = arow[kk];
        dot = fmaf(a.x, b.x, dot); ssq = fmaf(b.x, b.x, ssq);
        dot = fmaf(a.y, b.y, dot); ssq = fmaf(b.y, b.y, ssq);
        dot = fmaf(a.z, b.z, dot); ssq = fmaf(b.z, b.z, ssq);
        dot = fmaf(a.w, b.w, dot); ssq = fmaf(b.w, b.w, ssq);
    }
    g_val[(i0 + q) * T2n + j] = dot * rsqrtf(ssq);
}

// ---------------------------------------------------------------------------
// K2: fused build + loss. Grid (i,t) = (128,8); 256 threads (8 warps).
//   Phase 1: builds compacted smem pack {aw, |pos|}, SA, and loss(c=64)
//     (cand==sta => ct_val = dsum/8, t-independent).
//   Phase 2: thread = pair(0..31)*8 + chunk; candidates c0=pair, c1=pair+32.
//     Inner: one LDS.64 pack per 2 candidates; f via bfind + exponent-magic
//     int->float (no table, no CVT): f = 8388623.0f - bits(q | 0x4B000000).
//   Mirrors (65..128) algebraic: loss± = SA + Sq/16384 ± 2*sc*S2.
// ---------------------------------------------------------------------------
__device__ __forceinline__ int make_cand(int c, int stav, const int* rm, int i, int t) {
    int h = c >> 2, k = c & 3;
    int r = rm[((i * Hn + h) * Kn + k) * TPn + t];
    return (stav ^ (1 << h)) ^ (r & ((1 << h) - 1));
}

__global__ __launch_bounds__(256, 6) void k_mega(const int* __restrict__ sta,
                                                 const int* __restrict__ pos,
                                                 const unsigned* __restrict__ mask,
                                                 const int* __restrict__ rmask,
                                                 float* __restrict__ out) {
    int i = blockIdx.x, t = blockIdx.y;
    int tid = threadIdx.x;
    int lane = tid & 31, w = tid >> 5;          // 8 warps

    __shared__ float2 s_pk[T2n];                // 4 KB: {aw, bits(|pos|)}
    __shared__ int    s_st[TPn];
    __shared__ int    s_wcnt[16];
    __shared__ int    s_base[16];
    __shared__ int    s_cnt;
    __shared__ float  s_sared[8];
    __shared__ float  s_s64red[8];
    __shared__ float  s_SA;

    if (tid < TPn) s_st[tid] = sta[i * TPn + tid];
    __syncthreads();

    // ---- phase 1: build compacted pack + SA + loss64 ----
    unsigned ballR[2];
    float    awR[2];
    int      abR[2];
    bool     mR[2];
    float    sacc = 0.f, sacc64 = 0.f;
    #pragma unroll
    for (int rr = 0; rr < 2; rr++) {
        int j = rr * 256 + tid;
        int4 p0 = ((const int4*)pos)[j * 2];
        int4 p1 = ((const int4*)pos)[j * 2 + 1];
        int pv[TPn] = {p0.x, p0.y, p0.z, p0.w, p1.x, p1.y, p1.z, p1.w};
        bool m = (mask[i * T2n + j] != 0u);
        float val = g_val[i * T2n + j];

        float dsum = 0.f, dis_t = 0.f, spf_t = 1.f;
        int   ab_t = 0;
        #pragma unroll
        for (int tt = 0; tt < TPn; tt++) {
            int stt = s_st[tt];
            int a = stt < 0 ? -stt : stt;
            int b = pv[tt] < 0 ? -pv[tt] : pv[tt];
            float sg = ((stt ^ pv[tt]) < 0) ? -1.0f : 1.0f;
            int v = (a ^ b) + 1;
            int p; asm("bfind.u32 %0, %1;" : "=r"(p) : "r"(v));
            float d = sg * (float)(15 - p) * (1.0f / 16.0f);
            dsum += d;
            if (tt == t) { dis_t = d; ab_t = b; spf_t = (pv[tt] < 0) ? -1.0f : 1.0f; }
        }
        float A = (dsum - dis_t) * 0.125f - val;     // candidate-contribution base
        float B = dsum * 0.125f - val;               // c==sta (t-independent)
        awR[rr] = A * spf_t * (1.0f / 128.0f);
        abR[rr] = ab_t;
        mR[rr]  = m;
        ballR[rr] = __ballot_sync(0xffffffffu, m);
        if (m) { sacc = fmaf(A, A, sacc); sacc64 = fmaf(B, B, sacc64); }
    }
    if (lane == 0) { s_wcnt[w] = __popc(ballR[0]); s_wcnt[8 + w] = __popc(ballR[1]); }
    for (int o = 16; o; o >>= 1) {
        sacc   += __shfl_down_sync(0xffffffffu, sacc, o);
        sacc64 += __shfl_down_sync(0xffffffffu, sacc64, o);
    }
    if (lane == 0) { s_sared[w] = sacc; s_s64red[w] = sacc64; }
    __syncthreads();
    if (tid == 0) {
        int s = 0;
        #pragma unroll
        for (int x = 0; x < 16; x++) { s_base[x] = s; s += s_wcnt[x]; }
        s_cnt = s;
        float sa = 0.f, s64 = 0.f;
        #pragma unroll
        for (int x = 0; x < 8; x++) { sa += s_sared[x]; s64 += s_s64red[x]; }
        s_SA = sa;
        out[(i * Cn + 64) * TPn + t] = s64;   // c == sta column
    }
    __syncthreads();
    unsigned lt = (1u << lane) - 1u;
    #pragma unroll
    for (int rr = 0; rr < 2; rr++) {
        if (mR[rr]) {
            int slot = s_base[rr * 8 + w] + __popc(ballR[rr] & lt);
            s_pk[slot] = make_float2(awR[rr], __int_as_float(abR[rr]));
        }
    }
    __syncthreads();
    int cnt = s_cnt;

    // ---- phase 2: 64 res candidates, 2 per thread ----
    int pr = tid >> 3;                   // 0..31
    int chunk = tid & 7;
    int stav = s_st[t];
    int c0 = pr, c1 = pr + 32;
    int cand0 = make_cand(c0, stav, rmask, i, t);
    int cand1 = make_cand(c1, stav, rmask, i, t);
    int ac0 = cand0 < 0 ? -cand0 : cand0;
    int ac1 = cand1 < 0 ? -cand1 : cand1;

    float S20 = 0.f, Sq0 = 0.f, S21 = 0.f, Sq1 = 0.f;
    #pragma unroll 4
    for (int jj = chunk; jj < cnt; jj += 8) {
        float2 pk = s_pk[jj];
        int ap = __float_as_int(pk.y);
        int v0 = (ac0 ^ ap) + 1;
        int v1 = (ac1 ^ ap) + 1;
        int q0, q1;
        asm("bfind.u32 %0, %1;" : "=r"(q0) : "r"(v0));
        asm("bfind.u32 %0, %1;" : "=r"(q1) : "r"(v1));
        float f0 = 8388623.0f - __int_as_float(q0 | 0x4B000000);  // 15 - q0
        float f1 = 8388623.0f - __int_as_float(q1 | 0x4B000000);  // 15 - q1
        S20 = fmaf(pk.x, f0, S20);
        Sq0 = fmaf(f0, f0, Sq0);
        S21 = fmaf(pk.x, f1, S21);
        Sq1 = fmaf(f1, f1, Sq1);
    }
    #pragma unroll
    for (int o = 4; o; o >>= 1) {
        S20 += __shfl_down_sync(0xffffffffu, S20, o);
        Sq0 += __shfl_down_sync(0xffffffffu, Sq0, o);
        S21 += __shfl_down_sync(0xffffffffu, S21, o);
        Sq1 += __shfl_down_sync(0xffffffffu, Sq1, o);
    }

    if (chunk == 0) {
        float SA = s_SA;
        {
            float base = SA + Sq0 * (1.0f / 16384.0f);
            float sc   = cand0 < 0 ? -1.0f : 1.0f;
            float tw   = 2.0f * sc * S20;
            float lp   = base + tw;
            out[(i * Cn + c0) * TPn + t] = lp;
            out[(i * Cn + 65 + c0) * TPn + t] = (cand0 == 0) ? lp : (base - tw);
        }
        {
            float base = SA + Sq1 * (1.0f / 16384.0f);
            float sc   = cand1 < 0 ? -1.0f : 1.0f;
            float tw   = 2.0f * sc * S21;
            float lp   = base + tw;
            out[(i * Cn + c1) * TPn + t] = lp;
            out[(i * Cn + 65 + c1) * TPn + t] = (cand1 == 0) ? lp : (base - tw);
        }
    }
}

// ---------------------------------------------------------------------------
extern "C" void kernel_launch(void* const* d_in, const int* in_sizes, int n_in,
                              void* d_out, int out_size) {
    const float*    emb1 = (const float*)d_in[0];
    const float*    emb2 = (const float*)d_in[1];
    const int*      sta  = (const int*)d_in[2];
    const int*      pos  = (const int*)d_in[3];
    const unsigned* mask = (const unsigned*)d_in[4];
    const int*      rm   = (const int*)d_in[5];
    float*          out  = (float*)d_out;

    k_val<<<dim3(32, 4), 512>>>(emb1, emb2);
    k_mega<<<dim3(T1n, TPn), 256>>>(sta, pos, mask, rm, out);
}

// round 5
// speedup vs baseline: 1.4638x; 1.0652x over previous
#include <cuda_runtime.h>
#include <cuda_bf16.h>
#include <cstdint>

// ---- problem constants ----
#define T1n 128
#define T2n 512
#define TPn 8
#define Hn  16
#define Kn  4
#define Cn  129   // 2*K*H+1
#define Dn  256

// ---- device scratch ----
__device__ float g_val[T1n * T2n];   // val_v

// ---------------------------------------------------------------------------
// K1: val_v[i][j] = <e1_i/|e1_i|, e2_j/|e2_j|>.
//   Grid (32,4): block = 4 i-rows x 128 j-cols, 512 threads.
// ---------------------------------------------------------------------------
__global__ __launch_bounds__(512) void k_val(const float* __restrict__ e1,
                                             const float* __restrict__ e2) {
    int i0 = blockIdx.x * 4;
    int j0 = blockIdx.y * 128;
    int tid = threadIdx.x;
    int q = tid >> 7, r = tid & 127;

    __shared__ float s1[4][Dn];
    __shared__ float red[4][4];
    __shared__ float sinv[4];

    float a0 = e1[(i0 + q) * Dn + r];
    float a1 = e1[(i0 + q) * Dn + 128 + r];
    float ss = a0 * a0 + a1 * a1;
    for (int o = 16; o; o >>= 1) ss += __shfl_down_sync(0xffffffffu, ss, o);
    if ((r & 31) == 0) red[q][r >> 5] = ss;
    __syncthreads();
    if (tid < 4) sinv[tid] = rsqrtf(red[tid][0] + red[tid][1] + red[tid][2] + red[tid][3]);
    __syncthreads();
    float inv = sinv[q];
    s1[q][r] = a0 * inv;
    s1[q][r + 128] = a1 * inv;
    __syncthreads();

    int j = j0 + r;
    const float4* row  = (const float4*)(e2 + j * Dn);
    const float4* arow = (const float4*)(&s1[q][0]);
    float dot = 0.f, ssq = 0.f;
    #pragma unroll 8
    for (int kk = 0; kk < Dn / 4; kk++) {
        float4 b = row[kk];
        float4 a = arow[kk];
        dot = fmaf(a.x, b.x, dot); ssq = fmaf(b.x, b.x, ssq);
        dot = fmaf(a.y, b.y, dot); ssq = fmaf(b.y, b.y, ssq);
        dot = fmaf(a.z, b.z, dot); ssq = fmaf(b.z, b.z, ssq);
        dot = fmaf(a.w, b.w, dot); ssq = fmaf(b.w, b.w, ssq);
    }
    g_val[(i0 + q) * T2n + j] = dot * rsqrtf(ssq);
}

// ---------------------------------------------------------------------------
// K2: fused build + loss. Grid = 128 (one block per i); 1024 threads.
//   Phase 1 (tid<512, j=tid): ONE distance scan per i. Emits 8 per-t compacted
//     pack lists {aw_t, |pos_t|} (identical slot across t), SA_t, loss(c=64).
//   Phase 2 (all 1024): tid -> (t = tid>>7, pair = (tid>>2)&31, chunk = tid&3).
//     Candidates c0=pair, c1=pair+32 over jj = chunk..cnt step 4.
//     f via bfind + exponent-magic; mirrors algebraic.
// ---------------------------------------------------------------------------
__device__ __forceinline__ int make_cand(int c, int stav, const int* rm, int i, int t) {
    int h = c >> 2, k = c & 3;
    int r = rm[((i * Hn + h) * Kn + k) * TPn + t];
    return (stav ^ (1 << h)) ^ (r & ((1 << h) - 1));
}

__global__ __launch_bounds__(1024, 1) void k_mega(const int* __restrict__ sta,
                                                  const int* __restrict__ pos,
                                                  const unsigned* __restrict__ mask,
                                                  const int* __restrict__ rmask,
                                                  float* __restrict__ out) {
    int i = blockIdx.x;
    int tid = threadIdx.x;
    int lane = tid & 31, w = tid >> 5;

    __shared__ float2 s_pk[TPn][T2n];     // 32 KB: per-t {aw, bits(|pos|)}
    __shared__ int    s_st[TPn];
    __shared__ int    s_wcnt[16];
    __shared__ int    s_base[16];
    __shared__ int    s_cnt;
    __shared__ float  s_red[16][TPn];     // per-warp SA partials
    __shared__ float  s_red64[16];
    __shared__ float  s_SA[TPn];
    __shared__ float  s_L64;

    if (tid < TPn) s_st[tid] = sta[i * TPn + tid];
    __syncthreads();

    // ---- phase 1 ----
    if (tid < 512) {
        int j = tid;
        int4 p0 = ((const int4*)pos)[j * 2];
        int4 p1 = ((const int4*)pos)[j * 2 + 1];
        int pv[TPn] = {p0.x, p0.y, p0.z, p0.w, p1.x, p1.y, p1.z, p1.w};
        bool m = (mask[i * T2n + j] != 0u);
        float val = g_val[i * T2n + j];

        float dis[TPn];
        int   ab[TPn];
        float dsum = 0.f;
        #pragma unroll
        for (int tt = 0; tt < TPn; tt++) {
            int stt = s_st[tt];
            int a = stt < 0 ? -stt : stt;
            int b = pv[tt] < 0 ? -pv[tt] : pv[tt];
            ab[tt] = b;
            float sg = ((stt ^ pv[tt]) < 0) ? -1.0f : 1.0f;
            int v = (a ^ b) + 1;
            int p; asm("bfind.u32 %0, %1;" : "=r"(p) : "r"(v));
            float d = sg * (float)(15 - p) * (1.0f / 16.0f);
            dis[tt] = d;
            dsum += d;
        }

        unsigned ball = __ballot_sync(0xffffffffu, m);
        if (lane == 0) s_wcnt[w] = __popc(ball);

        float sacc[TPn], s64 = 0.f;
        float B = dsum * 0.125f - val;                 // c == sta (t-independent)
        if (m) s64 = B * B;
        #pragma unroll
        for (int tt = 0; tt < TPn; tt++) {
            float A = (dsum - dis[tt]) * 0.125f - val;
            sacc[tt] = m ? A * A : 0.0f;
        }
        // warp reductions
        #pragma unroll
        for (int o = 16; o; o >>= 1) {
            #pragma unroll
            for (int tt = 0; tt < TPn; tt++)
                sacc[tt] += __shfl_down_sync(0xffffffffu, sacc[tt], o);
            s64 += __shfl_down_sync(0xffffffffu, s64, o);
        }
        if (lane == 0) {
            #pragma unroll
            for (int tt = 0; tt < TPn; tt++) s_red[w][tt] = sacc[tt];
            s_red64[w] = s64;
        }
        __syncthreads();
        if (tid == 0) {
            int s = 0;
            #pragma unroll
            for (int x = 0; x < 16; x++) { s_base[x] = s; s += s_wcnt[x]; }
            s_cnt = s;
        }
        if (tid < TPn) {
            float s = 0.f;
            #pragma unroll
            for (int x = 0; x < 16; x++) s += s_red[x][tid];
            s_SA[tid] = s;
        }
        if (tid == TPn) {
            float s = 0.f;
            #pragma unroll
            for (int x = 0; x < 16; x++) s += s_red64[x];
            s_L64 = s;
        }
        __syncthreads();
        if (m) {
            int slot = s_base[w] + __popc(ball & ((1u << lane) - 1u));
            #pragma unroll
            for (int tt = 0; tt < TPn; tt++) {
                float A = (dsum - dis[tt]) * 0.125f - val;
                unsigned awb = __float_as_uint(A * (1.0f / 128.0f)) ^
                               ((unsigned)pv[tt] & 0x80000000u);
                s_pk[tt][slot] = make_float2(__uint_as_float(awb),
                                             __int_as_float(ab[tt]));
            }
        }
    } else {
        __syncthreads();
        __syncthreads();
    }
    __syncthreads();
    int cnt = s_cnt;

    // ---- phase 2 ----
    int t  = tid >> 7;                 // 0..7
    int r7 = tid & 127;
    int pr = r7 >> 2;                  // 0..31
    int chunk = r7 & 3;
    int stav = s_st[t];
    int c0 = pr, c1 = pr + 32;
    int cand0 = make_cand(c0, stav, rmask, i, t);
    int cand1 = make_cand(c1, stav, rmask, i, t);
    int ac0 = cand0 < 0 ? -cand0 : cand0;
    int ac1 = cand1 < 0 ? -cand1 : cand1;
    const float2* pk_t = s_pk[t];

    float S20 = 0.f, Sq0 = 0.f, S21 = 0.f, Sq1 = 0.f;
    #pragma unroll 4
    for (int jj = chunk; jj < cnt; jj += 4) {
        float2 pk = pk_t[jj];
        int ap = __float_as_int(pk.y);
        int v0 = (ac0 ^ ap) + 1;
        int v1 = (ac1 ^ ap) + 1;
        int q0, q1;
        asm("bfind.u32 %0, %1;" : "=r"(q0) : "r"(v0));
        asm("bfind.u32 %0, %1;" : "=r"(q1) : "r"(v1));
        float f0 = 8388623.0f - __int_as_float(q0 | 0x4B000000);  // 15 - q0
        float f1 = 8388623.0f - __int_as_float(q1 | 0x4B000000);  // 15 - q1
        S20 = fmaf(pk.x, f0, S20);
        Sq0 = fmaf(f0, f0, Sq0);
        S21 = fmaf(pk.x, f1, S21);
        Sq1 = fmaf(f1, f1, Sq1);
    }
    #pragma unroll
    for (int o = 2; o; o >>= 1) {
        S20 += __shfl_down_sync(0xffffffffu, S20, o);
        Sq0 += __shfl_down_sync(0xffffffffu, Sq0, o);
        S21 += __shfl_down_sync(0xffffffffu, S21, o);
        Sq1 += __shfl_down_sync(0xffffffffu, Sq1, o);
    }

    if (chunk == 0) {
        float SA = s_SA[t];
        {
            float base = SA + Sq0 * (1.0f / 16384.0f);
            float sc   = cand0 < 0 ? -1.0f : 1.0f;
            float tw   = 2.0f * sc * S20;
            float lp   = base + tw;
            out[(i * Cn + c0) * TPn + t] = lp;
            out[(i * Cn + 65 + c0) * TPn + t] = (cand0 == 0) ? lp : (base - tw);
        }
        {
            float base = SA + Sq1 * (1.0f / 16384.0f);
            float sc   = cand1 < 0 ? -1.0f : 1.0f;
            float tw   = 2.0f * sc * S21;
            float lp   = base + tw;
            out[(i * Cn + c1) * TPn + t] = lp;
            out[(i * Cn + 65 + c1) * TPn + t] = (cand1 == 0) ? lp : (base - tw);
        }
        if (pr == 0)
            out[(i * Cn + 64) * TPn + t] = s_L64;
    }
}

// ---------------------------------------------------------------------------
extern "C" void kernel_launch(void* const* d_in, const int* in_sizes, int n_in,
                              void* d_out, int out_size) {
    const float*    emb1 = (const float*)d_in[0];
    const float*    emb2 = (const float*)d_in[1];
    const int*      sta  = (const int*)d_in[2];
    const int*      pos  = (const int*)d_in[3];
    const unsigned* mask = (const unsigned*)d_in[4];
    const int*      rm   = (const int*)d_in[5];
    float*          out  = (float*)d_out;

    k_val<<<dim3(32, 4), 512>>>(emb1, emb2);
    k_mega<<<T1n, 1024>>>(sta, pos, mask, rm, out);
}

// round 6
// speedup vs baseline: 1.4651x; 1.0009x over previous
#include <cuda_runtime.h>
#include <cuda_bf16.h>
#include <cstdint>

// ---- problem constants ----
#define T1n 128
#define T2n 512
#define TPn 8
#define Hn  16
#define Kn  4
#define Cn  129   // 2*K*H+1
#define Dn  256

// ---- device scratch ----
__device__ float g_val[T1n * T2n];   // val_v

// ---------------------------------------------------------------------------
// K1: val_v[i][j] = <e1_i/|e1_i|, e2_j/|e2_j|>.
//   Grid (32,4): block = 4 i-rows x 128 j-cols, 512 threads.
// ---------------------------------------------------------------------------
__global__ __launch_bounds__(512) void k_val(const float* __restrict__ e1,
                                             const float* __restrict__ e2) {
    int i0 = blockIdx.x * 4;
    int j0 = blockIdx.y * 128;
    int tid = threadIdx.x;
    int q = tid >> 7, r = tid & 127;

    __shared__ float s1[4][Dn];
    __shared__ float red[4][4];
    __shared__ float sinv[4];

    float a0 = e1[(i0 + q) * Dn + r];
    float a1 = e1[(i0 + q) * Dn + 128 + r];
    float ss = a0 * a0 + a1 * a1;
    for (int o = 16; o; o >>= 1) ss += __shfl_down_sync(0xffffffffu, ss, o);
    if ((r & 31) == 0) red[q][r >> 5] = ss;
    __syncthreads();
    if (tid < 4) sinv[tid] = rsqrtf(red[tid][0] + red[tid][1] + red[tid][2] + red[tid][3]);
    __syncthreads();
    float inv = sinv[q];
    s1[q][r] = a0 * inv;
    s1[q][r + 128] = a1 * inv;
    __syncthreads();

    int j = j0 + r;
    const float4* row  = (const float4*)(e2 + j * Dn);
    const float4* arow = (const float4*)(&s1[q][0]);
    float dot = 0.f, ssq = 0.f;
    #pragma unroll 8
    for (int kk = 0; kk < Dn / 4; kk++) {
        float4 b = row[kk];
        float4 a = arow[kk];
        dot = fmaf(a.x, b.x, dot); ssq = fmaf(b.x, b.x, ssq);
        dot = fmaf(a.y, b.y, dot); ssq = fmaf(b.y, b.y, ssq);
        dot = fmaf(a.z, b.z, dot); ssq = fmaf(b.z, b.z, ssq);
        dot = fmaf(a.w, b.w, dot); ssq = fmaf(b.w, b.w, ssq);
    }
    g_val[(i0 + q) * T2n + j] = dot * rsqrtf(ssq);
}

// ---------------------------------------------------------------------------
// K2: fused build + loss. Grid (i, tg) = (128, 2); 512 threads, 2 blocks/SM.
//   Block handles t in [tg*4, tg*4+4).
//   Phase 1 (j = tid): one distance scan (all 8 t for dsum), emits 4 per-t
//     compacted pack lists {aw_t (sign-folded), |pos_t|}, SA_t, loss(c=64).
//   Phase 2: tid -> (tl = tid>>7, pair = (tid>>2)&31, chunk = tid&3);
//     candidates c0=pair, c1=pair+32; f via bfind + exponent-magic FADD;
//     mirrors (65..128) algebraic: loss± = SA + Sq/16384 ± 2*sc*S2.
// ---------------------------------------------------------------------------
__device__ __forceinline__ int make_cand(int c, int stav, const int* rm, int i, int t) {
    int h = c >> 2, k = c & 3;
    int r = rm[((i * Hn + h) * Kn + k) * TPn + t];
    return (stav ^ (1 << h)) ^ (r & ((1 << h) - 1));
}

__global__ __launch_bounds__(512, 2) void k_mega(const int* __restrict__ sta,
                                                 const int* __restrict__ pos,
                                                 const unsigned* __restrict__ mask,
                                                 const int* __restrict__ rmask,
                                                 float* __restrict__ out) {
    int i  = blockIdx.x;
    int tg = blockIdx.y;                  // 0 or 1: t in [tg*4, tg*4+4)
    int t0 = tg * 4;
    int tid = threadIdx.x;
    int lane = tid & 31, w = tid >> 5;    // 16 warps

    __shared__ float2 s_pk[4][T2n];       // 16 KB: per-local-t {aw, bits(|pos|)}
    __shared__ int    s_st[TPn];
    __shared__ int    s_wcnt[16];
    __shared__ int    s_base[16];
    __shared__ int    s_cnt;
    __shared__ float  s_red[16][5];       // per-warp partials: SA[4], s64
    __shared__ float  s_SA[4];
    __shared__ float  s_L64;

    if (tid < TPn) s_st[tid] = sta[i * TPn + tid];
    __syncthreads();

    // ---- phase 1: every thread owns one j ----
    {
        int j = tid;
        int4 p0 = ((const int4*)pos)[j * 2];
        int4 p1 = ((const int4*)pos)[j * 2 + 1];
        int pv[TPn] = {p0.x, p0.y, p0.z, p0.w, p1.x, p1.y, p1.z, p1.w};
        bool m = (mask[i * T2n + j] != 0u);
        float val = g_val[i * T2n + j];

        float dis[TPn];
        int   ab[TPn];
        float dsum = 0.f;
        #pragma unroll
        for (int tt = 0; tt < TPn; tt++) {
            int stt = s_st[tt];
            int a = stt < 0 ? -stt : stt;
            int b = pv[tt] < 0 ? -pv[tt] : pv[tt];
            ab[tt] = b;
            float sg = ((stt ^ pv[tt]) < 0) ? -1.0f : 1.0f;
            int v = (a ^ b) + 1;
            int p; asm("bfind.u32 %0, %1;" : "=r"(p) : "r"(v));
            float d = sg * (float)(15 - p) * (1.0f / 16.0f);
            dis[tt] = d;
            dsum += d;
        }

        unsigned ball = __ballot_sync(0xffffffffu, m);
        if (lane == 0) s_wcnt[w] = __popc(ball);

        float red5[5];
        {
            float B = dsum * 0.125f - val;          // c == sta (t-independent)
            red5[4] = m ? B * B : 0.0f;
            #pragma unroll
            for (int tl = 0; tl < 4; tl++) {
                float A = (dsum - dis[t0 + tl]) * 0.125f - val;
                red5[tl] = m ? A * A : 0.0f;
            }
        }
        #pragma unroll
        for (int o = 16; o; o >>= 1) {
            #pragma unroll
            for (int x = 0; x < 5; x++)
                red5[x] += __shfl_down_sync(0xffffffffu, red5[x], o);
        }
        if (lane == 0) {
            #pragma unroll
            for (int x = 0; x < 5; x++) s_red[w][x] = red5[x];
        }
        __syncthreads();
        if (tid == 0) {
            int s = 0;
            #pragma unroll
            for (int x = 0; x < 16; x++) { s_base[x] = s; s += s_wcnt[x]; }
            s_cnt = s;
        }
        if (tid < 4) {
            float s = 0.f;
            #pragma unroll
            for (int x = 0; x < 16; x++) s += s_red[x][tid];
            s_SA[tid] = s;
        }
        if (tid == 4) {
            float s = 0.f;
            #pragma unroll
            for (int x = 0; x < 16; x++) s += s_red[x][4];
            s_L64 = s;
        }
        __syncthreads();
        if (m) {
            int slot = s_base[w] + __popc(ball & ((1u << lane) - 1u));
            #pragma unroll
            for (int tl = 0; tl < 4; tl++) {
                int tt = t0 + tl;
                float A = (dsum - dis[tt]) * 0.125f - val;
                unsigned awb = __float_as_uint(A * (1.0f / 128.0f)) ^
                               ((unsigned)pv[tt] & 0x80000000u);
                s_pk[tl][slot] = make_float2(__uint_as_float(awb),
                                             __int_as_float(ab[tt]));
            }
        }
    }
    __syncthreads();
    int cnt = s_cnt;

    // ---- phase 2 ----
    int tl = tid >> 7;                 // 0..3
    int t  = t0 + tl;
    int r7 = tid & 127;
    int pr = r7 >> 2;                  // 0..31
    int chunk = r7 & 3;
    int stav = s_st[t];
    int c0 = pr, c1 = pr + 32;
    int cand0 = make_cand(c0, stav, rmask, i, t);
    int cand1 = make_cand(c1, stav, rmask, i, t);
    int ac0 = cand0 < 0 ? -cand0 : cand0;
    int ac1 = cand1 < 0 ? -cand1 : cand1;
    const float2* pk_t = s_pk[tl];

    float S20 = 0.f, Sq0 = 0.f, S21 = 0.f, Sq1 = 0.f;
    #pragma unroll 4
    for (int jj = chunk; jj < cnt; jj += 4) {
        float2 pk = pk_t[jj];
        int ap = __float_as_int(pk.y);
        int v0 = (ac0 ^ ap) + 1;
        int v1 = (ac1 ^ ap) + 1;
        int q0, q1;
        asm("bfind.u32 %0, %1;" : "=r"(q0) : "r"(v0));
        asm("bfind.u32 %0, %1;" : "=r"(q1) : "r"(v1));
        float f0 = 8388623.0f - __int_as_float(q0 | 0x4B000000);  // 15 - q0
        float f1 = 8388623.0f - __int_as_float(q1 | 0x4B000000);  // 15 - q1
        S20 = fmaf(pk.x, f0, S20);
        Sq0 = fmaf(f0, f0, Sq0);
        S21 = fmaf(pk.x, f1, S21);
        Sq1 = fmaf(f1, f1, Sq1);
    }
    #pragma unroll
    for (int o = 2; o; o >>= 1) {
        S20 += __shfl_down_sync(0xffffffffu, S20, o);
        Sq0 += __shfl_down_sync(0xffffffffu, Sq0, o);
        S21 += __shfl_down_sync(0xffffffffu, S21, o);
        Sq1 += __shfl_down_sync(0xffffffffu, Sq1, o);
    }

    if (chunk == 0) {
        float SA = s_SA[tl];
        {
            float base = SA + Sq0 * (1.0f / 16384.0f);
            float sc   = cand0 < 0 ? -1.0f : 1.0f;
            float tw   = 2.0f * sc * S20;
            float lp   = base + tw;
            out[(i * Cn + c0) * TPn + t] = lp;
            out[(i * Cn + 65 + c0) * TPn + t] = (cand0 == 0) ? lp : (base - tw);
        }
        {
            float base = SA + Sq1 * (1.0f / 16384.0f);
            float sc   = cand1 < 0 ? -1.0f : 1.0f;
            float tw   = 2.0f * sc * S21;
            float lp   = base + tw;
            out[(i * Cn + c1) * TPn + t] = lp;
            out[(i * Cn + 65 + c1) * TPn + t] = (cand1 == 0) ? lp : (base - tw);
        }
        if (pr == 0)
            out[(i * Cn + 64) * TPn + t] = s_L64;
    }
}

// ---------------------------------------------------------------------------
extern "C" void kernel_launch(void* const* d_in, const int* in_sizes, int n_in,
                              void* d_out, int out_size) {
    const float*    emb1 = (const float*)d_in[0];
    const float*    emb2 = (const float*)d_in[1];
    const int*      sta  = (const int*)d_in[2];
    const int*      pos  = (const int*)d_in[3];
    const unsigned* mask = (const unsigned*)d_in[4];
    const int*      rm   = (const int*)d_in[5];
    float*          out  = (float*)d_out;

    k_val<<<dim3(32, 4), 512>>>(emb1, emb2);
    k_mega<<<dim3(T1n, 2), 512>>>(sta, pos, mask, rm, out);
}

// round 7
// speedup vs baseline: 1.4908x; 1.0175x over previous
#include <cuda_runtime.h>
#include <cuda_bf16.h>
#include <cstdint>

// ---- problem constants ----
#define T1n 128
#define T2n 512
#define TPn 8
#define Hn  16
#define Kn  4
#define Cn  129   // 2*K*H+1
#define Dn  256

// ---- device scratch ----
__device__ uint2 g_pack[T1n * TPn * T2n];  // {bits(aw sign-folded), |pos| | maskbit}
__device__ float g_mB2[T1n * T2n];         // m * B^2  (B = dsum/8 - val)

// ---------------------------------------------------------------------------
// K1: fused val + pack build. Grid (32,4): block = 4 i-rows x 128 j-cols.
//   Per thread (q = i-local, r = j-local):
//     val = <e1_i/|e1_i|, e2_j/|e2_j|>  (e1 row normalized in smem; e2 row
//     streamed with inline ssq), then the 8-way distance scan, emitting:
//       g_pack[(i,t,j)] = {bits(A_t/128) ^ sign(pos_t),  |pos_t| | (!m << 31)}
//       g_mB2[i,j]      = m * (dsum/8 - val)^2
// ---------------------------------------------------------------------------
__global__ __launch_bounds__(512) void k_valbuild(const float* __restrict__ e1,
                                                  const float* __restrict__ e2,
                                                  const int* __restrict__ sta,
                                                  const int* __restrict__ pos,
                                                  const unsigned* __restrict__ mask) {
    int i0 = blockIdx.x * 4;
    int j0 = blockIdx.y * 128;
    int tid = threadIdx.x;
    int q = tid >> 7, r = tid & 127;
    int i = i0 + q, j = j0 + r;

    __shared__ float s1[4][Dn];
    __shared__ float red[4][4];
    __shared__ float sinv[4];
    __shared__ int   s_sta[4][TPn];

    // e1 row norms (4 rows) + sta preload
    float a0 = e1[i * Dn + r];
    float a1 = e1[i * Dn + 128 + r];
    float ss = a0 * a0 + a1 * a1;
    for (int o = 16; o; o >>= 1) ss += __shfl_down_sync(0xffffffffu, ss, o);
    if ((r & 31) == 0) red[q][r >> 5] = ss;
    if (tid < 32) s_sta[tid >> 3][tid & 7] = sta[(i0 + (tid >> 3)) * TPn + (tid & 7)];
    __syncthreads();
    if (tid < 4) sinv[tid] = rsqrtf(red[tid][0] + red[tid][1] + red[tid][2] + red[tid][3]);
    __syncthreads();
    float inv = sinv[q];
    s1[q][r] = a0 * inv;
    s1[q][r + 128] = a1 * inv;
    __syncthreads();

    // dot + e2 ssq
    const float4* row  = (const float4*)(e2 + j * Dn);
    const float4* arow = (const float4*)(&s1[q][0]);
    float dot = 0.f, ssq = 0.f;
    #pragma unroll 8
    for (int kk = 0; kk < Dn / 4; kk++) {
        float4 b = row[kk];
        float4 a = arow[kk];
        dot = fmaf(a.x, b.x, dot); ssq = fmaf(b.x, b.x, ssq);
        dot = fmaf(a.y, b.y, dot); ssq = fmaf(b.y, b.y, ssq);
        dot = fmaf(a.z, b.z, dot); ssq = fmaf(b.z, b.z, ssq);
        dot = fmaf(a.w, b.w, dot); ssq = fmaf(b.w, b.w, ssq);
    }
    float val = dot * rsqrtf(ssq);

    // distance scan
    int4 p0 = ((const int4*)pos)[j * 2];
    int4 p1 = ((const int4*)pos)[j * 2 + 1];
    int pv[TPn] = {p0.x, p0.y, p0.z, p0.w, p1.x, p1.y, p1.z, p1.w};
    bool m = (mask[i * T2n + j] != 0u);

    float dis[TPn];
    int   ab[TPn];
    float dsum = 0.f;
    #pragma unroll
    for (int tt = 0; tt < TPn; tt++) {
        int stt = s_sta[q][tt];
        int a = stt < 0 ? -stt : stt;
        int b = pv[tt] < 0 ? -pv[tt] : pv[tt];
        ab[tt] = b;
        float sg = ((stt ^ pv[tt]) < 0) ? -1.0f : 1.0f;
        int v = (a ^ b) + 1;
        int p; asm("bfind.u32 %0, %1;" : "=r"(p) : "r"(v));
        float d = sg * (float)(15 - p) * (1.0f / 16.0f);
        dis[tt] = d;
        dsum += d;
    }

    float B = dsum * 0.125f - val;
    g_mB2[i * T2n + j] = m ? B * B : 0.0f;

    unsigned mtag = m ? 0u : 0x80000000u;
    #pragma unroll
    for (int tt = 0; tt < TPn; tt++) {
        float A = (dsum - dis[tt]) * 0.125f - val;
        unsigned awb = __float_as_uint(A * (1.0f / 128.0f)) ^
                       ((unsigned)pv[tt] & 0x80000000u);
        g_pack[(i * TPn + tt) * T2n + j] =
            make_uint2(awb, (unsigned)ab[tt] | mtag);
    }
}

// ---------------------------------------------------------------------------
// K2: loss kernel. Grid (i,t) = (128,8); 256 threads (8 warps), 6 blocks/SM.
//   Preload: load 512 pack entries, ballot-compact masked-in into smem,
//     SA = 16384 * sum(aw^2); block t==0 additionally reduces g_mB2 -> loss64.
//   Phase 2: pr = tid>>3 (0..31), chunk = tid&7; candidates c0=pr, c1=pr+32.
//     c0 uses the I2F/exponent path, c1 uses FLO — splits work across pipes.
//   Mirrors (65..128) algebraic: loss± = SA + Sq/16384 ± 2*sc*S2.
// ---------------------------------------------------------------------------
__device__ __forceinline__ int make_cand(int c, int stav, const int* rm, int i, int t) {
    int h = c >> 2, k = c & 3;
    int r = rm[((i * Hn + h) * Kn + k) * TPn + t];
    return (stav ^ (1 << h)) ^ (r & ((1 << h) - 1));
}

__global__ __launch_bounds__(256, 6) void k_loss(const int* __restrict__ sta,
                                                 const int* __restrict__ rmask,
                                                 float* __restrict__ out) {
    int i = blockIdx.x, t = blockIdx.y;
    int tid = threadIdx.x;
    int lane = tid & 31, w = tid >> 5;          // 8 warps

    __shared__ uint2 s_pk[T2n];                 // 4 KB
    __shared__ int   s_wcnt[16];
    __shared__ int   s_base[16];
    __shared__ int   s_cnt;
    __shared__ float s_red[8], s_red64[8];
    __shared__ float s_SA, s_L64;

    const uint2* gp = g_pack + (i * TPn + t) * T2n;

    unsigned ballR[2];
    uint2    pkR[2];
    bool     mR[2];
    float    sacc = 0.f, l64 = 0.f;
    #pragma unroll
    for (int rr = 0; rr < 2; rr++) {
        uint2 pk = gp[rr * 256 + tid];
        bool m = ((int)pk.y) >= 0;
        if (m) { float aw = __uint_as_float(pk.x); sacc = fmaf(aw, aw, sacc); }
        ballR[rr] = __ballot_sync(0xffffffffu, m);
        pkR[rr] = pk; mR[rr] = m;
    }
    if (t == 0)
        l64 = g_mB2[i * T2n + tid] + g_mB2[i * T2n + 256 + tid];
    if (lane == 0) { s_wcnt[w] = __popc(ballR[0]); s_wcnt[8 + w] = __popc(ballR[1]); }
    for (int o = 16; o; o >>= 1) {
        sacc += __shfl_down_sync(0xffffffffu, sacc, o);
        l64  += __shfl_down_sync(0xffffffffu, l64, o);
    }
    if (lane == 0) { s_red[w] = sacc; s_red64[w] = l64; }
    __syncthreads();
    if (tid == 0) {
        int s = 0;
        #pragma unroll
        for (int x = 0; x < 16; x++) { s_base[x] = s; s += s_wcnt[x]; }
        s_cnt = s;
        float sa = 0.f, s64 = 0.f;
        #pragma unroll
        for (int x = 0; x < 8; x++) { sa += s_red[x]; s64 += s_red64[x]; }
        s_SA = 16384.0f * sa;
        s_L64 = s64;
    }
    __syncthreads();
    unsigned lt = (1u << lane) - 1u;
    #pragma unroll
    for (int rr = 0; rr < 2; rr++) {
        if (mR[rr]) {
            int slot = s_base[rr * 8 + w] + __popc(ballR[rr] & lt);
            s_pk[slot] = pkR[rr];
        }
    }
    __syncthreads();
    int cnt = s_cnt;

    // ---- phase 2 ----
    int pr = tid >> 3;                  // 0..31
    int chunk = tid & 7;
    int stav = sta[i * TPn + t];
    int c0 = pr, c1 = pr + 32;
    int cand0 = make_cand(c0, stav, rmask, i, t);
    int cand1 = make_cand(c1, stav, rmask, i, t);
    unsigned ac0 = (unsigned)(cand0 < 0 ? -cand0 : cand0);
    unsigned ac1 = (unsigned)(cand1 < 0 ? -cand1 : cand1);

    float S20 = 0.f, Sq0 = 0.f, S21 = 0.f, Sq1 = 0.f;
    #pragma unroll 4
    for (int jj = chunk; jj < cnt; jj += 8) {
        uint2 pk = s_pk[jj];
        float aw = __uint_as_float(pk.x);
        unsigned ap = pk.y;
        // cand0: I2F path (rate-2 I2FP + SHF + LOP3 + FADD)
        unsigned v0 = (ac0 ^ ap) + 1u;
        float g0 = __uint2float_rn(v0);                    // exact, v0 <= 2^17
        unsigned eb0 = __float_as_uint(g0) >> 23;          // 127 + bfind(v0)
        float f0 = 8388750.0f - __uint_as_float(eb0 | 0x4B000000u);  // 15 - bfind
        // cand1: FLO path
        unsigned v1 = (ac1 ^ ap) + 1u;
        int q1; asm("bfind.u32 %0, %1;" : "=r"(q1) : "r"(v1));
        float f1 = 8388623.0f - __int_as_float(q1 | 0x4B000000);     // 15 - q1
        S20 = fmaf(aw, f0, S20);
        Sq0 = fmaf(f0, f0, Sq0);
        S21 = fmaf(aw, f1, S21);
        Sq1 = fmaf(f1, f1, Sq1);
    }
    #pragma unroll
    for (int o = 4; o; o >>= 1) {
        S20 += __shfl_down_sync(0xffffffffu, S20, o);
        Sq0 += __shfl_down_sync(0xffffffffu, Sq0, o);
        S21 += __shfl_down_sync(0xffffffffu, S21, o);
        Sq1 += __shfl_down_sync(0xffffffffu, Sq1, o);
    }

    if (chunk == 0) {
        float SA = s_SA;
        {
            float base = SA + Sq0 * (1.0f / 16384.0f);
            float sc   = cand0 < 0 ? -1.0f : 1.0f;
            float tw   = 2.0f * sc * S20;
            float lp   = base + tw;
            out[(i * Cn + c0) * TPn + t] = lp;
            out[(i * Cn + 65 + c0) * TPn + t] = (cand0 == 0) ? lp : (base - tw);
        }
        {
            float base = SA + Sq1 * (1.0f / 16384.0f);
            float sc   = cand1 < 0 ? -1.0f : 1.0f;
            float tw   = 2.0f * sc * S21;
            float lp   = base + tw;
            out[(i * Cn + c1) * TPn + t] = lp;
            out[(i * Cn + 65 + c1) * TPn + t] = (cand1 == 0) ? lp : (base - tw);
        }
        if (t == 0 && pr == 0) {
            float s64 = s_L64;
            #pragma unroll
            for (int tt = 0; tt < TPn; tt++)
                out[(i * Cn + 64) * TPn + tt] = s64;
        }
    }
}

// ---------------------------------------------------------------------------
extern "C" void kernel_launch(void* const* d_in, const int* in_sizes, int n_in,
                              void* d_out, int out_size) {
    const float*    emb1 = (const float*)d_in[0];
    const float*    emb2 = (const float*)d_in[1];
    const int*      sta  = (const int*)d_in[2];
    const int*      pos  = (const int*)d_in[3];
    const unsigned* mask = (const unsigned*)d_in[4];
    const int*      rm   = (const int*)d_in[5];
    float*          out  = (float*)d_out;

    k_valbuild<<<dim3(32, 4), 512>>>(emb1, emb2, sta, pos, mask);
    k_loss<<<dim3(T1n, TPn), 256>>>(sta, rm, out);
}